// round 15
// baseline (speedup 1.0000x reference)
#include <cuda_runtime.h>
#include <cuda_fp16.h>
#include <cuda_bf16.h>
#include <cstdint>

// Problem constants (fixed shapes)
#define B 8
#define N 2048
#define F 128            // F_IN == F_OUT == 128
#define MAXN 192         // max neighbors per row (mean ~42)
#define ALPHA 0.2f

// Scratch (no cudaMalloc allowed)
__device__ __align__(16) __half g_hh[B * N * F];   // 4 MB, fp16 copy of h
__device__ float g_esrc[B * N];
__device__ float g_edst[B * N];
__device__ __align__(16) int g_nbr[N * MAXN];
__device__ int   g_nnz[N];

// ---------------------------------------------------------------------------
// mma / ldmatrix helpers
// ---------------------------------------------------------------------------
__device__ __forceinline__ void ldsm_x4(uint32_t* r, uint32_t addr) {
    asm volatile("ldmatrix.sync.aligned.m8n8.x4.shared.b16 {%0,%1,%2,%3}, [%4];"
                 : "=r"(r[0]), "=r"(r[1]), "=r"(r[2]), "=r"(r[3]) : "r"(addr));
}
__device__ __forceinline__ void ldsm_x4_t(uint32_t* r, uint32_t addr) {
    asm volatile("ldmatrix.sync.aligned.m8n8.x4.trans.shared.b16 {%0,%1,%2,%3}, [%4];"
                 : "=r"(r[0]), "=r"(r[1]), "=r"(r[2]), "=r"(r[3]) : "r"(addr));
}
__device__ __forceinline__ void mma_bf16(float* c, const uint32_t* a,
                                         uint32_t b0, uint32_t b1) {
    asm volatile(
        "mma.sync.aligned.m16n8k16.row.col.f32.bf16.bf16.f32 "
        "{%0,%1,%2,%3}, {%4,%5,%6,%7}, {%8,%9}, {%0,%1,%2,%3};"
        : "+f"(c[0]), "+f"(c[1]), "+f"(c[2]), "+f"(c[3])
        : "r"(a[0]), "r"(a[1]), "r"(a[2]), "r"(a[3]), "r"(b0), "r"(b1));
}
__device__ __forceinline__ uint32_t pack_bf16(__nv_bfloat16 a, __nv_bfloat16 b) {
    __nv_bfloat162 t;
    t.x = a; t.y = b;
    return *reinterpret_cast<uint32_t*>(&t);
}

// ---------------------------------------------------------------------------
// Fat kernel (256 thr = 8 warps):
//   blocks [0,256)    -> adj bitmask compaction, 8 rows each (1/warp) [first:
//                        starts the 16MB DRAM scan at wave-front]
//   blocks [256,512)  -> bf16-split mma GEMM, 64 rows each (warp = 16r x 64c)
//                        with register-prefetch of the next K chunk
// ---------------------------------------------------------------------------
#define ADJ_BLOCKS 256
#define GEMM_BLOCKS 256
#define TM 64
#define KCH 32
#define XSTR 40      // bf16 elems per X smem row
#define WSTR 136     // bf16 elems per W smem row

__global__ __launch_bounds__(256) void fused_gemm_adj_kernel(
    const float* __restrict__ x,
    const float* __restrict__ adj,
    const float* __restrict__ W,
    const float* __restrict__ a_src,
    const float* __restrict__ a_dst) {

    if (blockIdx.x < ADJ_BLOCKS) {
        // ------- adjacency: single-pass bitmask compaction, warp per row -----
        int i = blockIdx.x * 8 + (threadIdx.x >> 5);
        int lane = threadIdx.x & 31;
        const float4* row4 = reinterpret_cast<const float4*>(adj + (size_t)i * N);
        unsigned msk0 = 0u, msk1 = 0u;
        int cnt = 0;
#pragma unroll
        for (int q = 0; q < 16; q++) {
            float4 v = row4[lane * 16 + q];
            int base = q * 4;
            float vv[4] = {v.x, v.y, v.z, v.w};
#pragma unroll
            for (int k = 0; k < 4; k++) {
                int bit = base + k;
                bool p = (vv[k] != 0.f) || (lane * 64 + bit == i);
                if (p) {
                    if (bit < 32) msk0 |= (1u << bit);
                    else          msk1 |= (1u << (bit - 32));
                    cnt++;
                }
            }
        }
        int off = cnt;
#pragma unroll
        for (int d = 1; d < 32; d <<= 1) {
            int t = __shfl_up_sync(0xFFFFFFFFu, off, d);
            if (lane >= d) off += t;
        }
        int total = __shfl_sync(0xFFFFFFFFu, off, 31);
        off -= cnt;
        int pos = off;
        unsigned mm = msk0;
        while (mm) {
            int bit = __ffs(mm) - 1;
            mm &= mm - 1;
            if (pos < MAXN) g_nbr[i * MAXN + pos] = lane * 64 + bit;
            pos++;
        }
        mm = msk1;
        while (mm) {
            int bit = __ffs(mm) - 1;
            mm &= mm - 1;
            if (pos < MAXN) g_nbr[i * MAXN + pos] = lane * 64 + 32 + bit;
            pos++;
        }
        if (lane == 31) g_nnz[i] = total < MAXN ? total : MAXN;
        return;
    }

    // ---------------- GEMM path: 8 warps, warp = 16 rows x 64 cols ----------
    __shared__ __align__(16) __nv_bfloat16 Xhi[TM * XSTR];
    __shared__ __align__(16) __nv_bfloat16 Xlo[TM * XSTR];
    __shared__ __align__(16) __nv_bfloat16 Whi[KCH * WSTR];
    __shared__ __align__(16) __nv_bfloat16 Wlo[KCH * WSTR];
    __shared__ float s_es[2][TM];   // edge partials per N-half
    __shared__ float s_ed[2][TM];

    const int tid = threadIdx.x;
    const int w = tid >> 5;
    const int lane = tid & 31;
    const int wr = w >> 1;         // row group 0..3 (16 rows each)
    const int wc = w & 1;          // col half 0..1 (64 cols each)
    const int m0 = (blockIdx.x - ADJ_BLOCKS) * TM;

    const int lm = lane >> 3;
    const int lr = lane & 7;
    const int arow = wr * 16 + ((lm & 1) << 3) + lr;
    const int acol = (lm >> 1) << 3;
    const int bk = ((lm & 1) << 3) + lr;
    const int bn = (lm >> 1) << 3;

    const uint32_t xhi_b = (uint32_t)__cvta_generic_to_shared(Xhi);
    const uint32_t xlo_b = (uint32_t)__cvta_generic_to_shared(Xlo);
    const uint32_t whi_b = (uint32_t)__cvta_generic_to_shared(Whi);
    const uint32_t wlo_b = (uint32_t)__cvta_generic_to_shared(Wlo);

    // Per-thread load coordinates (constant across chunks)
    const int xrow0 = tid >> 3,  xc4_0 = tid & 7;          // it = 0
    const int xrow1 = (tid + 256) >> 3, xc4_1 = (tid + 256) & 7;  // it = 1

    float c[8][4];
#pragma unroll
    for (int nt = 0; nt < 8; nt++)
#pragma unroll
        for (int q = 0; q < 4; q++) c[nt][q] = 0.f;

    // ---- preload chunk 0 into registers ----
    float4 xf[2], wf[4];
    xf[0] = reinterpret_cast<const float4*>(x + (size_t)(m0 + xrow0) * F)[xc4_0];
    xf[1] = reinterpret_cast<const float4*>(x + (size_t)(m0 + xrow1) * F)[xc4_1];
#pragma unroll
    for (int it = 0; it < 4; it++) {
        int l = tid + it * 256;
        wf[it] = reinterpret_cast<const float4*>(W + (size_t)(l >> 5) * F)[l & 31];
    }

#pragma unroll
    for (int kc = 0; kc < 4; kc++) {
        const int k0 = kc * KCH;
        // ---- convert + store current chunk from registers ----
#pragma unroll
        for (int it = 0; it < 2; it++) {
            int row = it ? xrow1 : xrow0;
            int c4 = it ? xc4_1 : xc4_0;
            float vv[4] = {xf[it].x, xf[it].y, xf[it].z, xf[it].w};
            __nv_bfloat16 hi[4], lo[4];
#pragma unroll
            for (int j = 0; j < 4; j++) {
                hi[j] = __float2bfloat16_rn(vv[j]);
                lo[j] = __float2bfloat16_rn(vv[j] - __bfloat162float(hi[j]));
            }
            int eoff = row * XSTR + c4 * 4;
            uint2 ph = {pack_bf16(hi[0], hi[1]), pack_bf16(hi[2], hi[3])};
            uint2 pl = {pack_bf16(lo[0], lo[1]), pack_bf16(lo[2], lo[3])};
            *reinterpret_cast<uint2*>(Xhi + eoff) = ph;
            *reinterpret_cast<uint2*>(Xlo + eoff) = pl;
        }
#pragma unroll
        for (int it = 0; it < 4; it++) {
            int l = tid + it * 256;
            int kk = l >> 5;
            int c4 = l & 31;
            float vv[4] = {wf[it].x, wf[it].y, wf[it].z, wf[it].w};
            __nv_bfloat16 hi[4], lo[4];
#pragma unroll
            for (int j = 0; j < 4; j++) {
                hi[j] = __float2bfloat16_rn(vv[j]);
                lo[j] = __float2bfloat16_rn(vv[j] - __bfloat162float(hi[j]));
            }
            int eoff = kk * WSTR + c4 * 4;
            uint2 ph = {pack_bf16(hi[0], hi[1]), pack_bf16(hi[2], hi[3])};
            uint2 pl = {pack_bf16(lo[0], lo[1]), pack_bf16(lo[2], lo[3])};
            *reinterpret_cast<uint2*>(Whi + eoff) = ph;
            *reinterpret_cast<uint2*>(Wlo + eoff) = pl;
        }
        __syncthreads();

        // ---- issue next-chunk loads (latency hidden behind mma) ----
        if (kc < 3) {
            const int kn = k0 + KCH;
            xf[0] = reinterpret_cast<const float4*>(
                x + (size_t)(m0 + xrow0) * F + kn)[xc4_0];
            xf[1] = reinterpret_cast<const float4*>(
                x + (size_t)(m0 + xrow1) * F + kn)[xc4_1];
#pragma unroll
            for (int it = 0; it < 4; it++) {
                int l = tid + it * 256;
                wf[it] = reinterpret_cast<const float4*>(
                    W + (size_t)(kn + (l >> 5)) * F)[l & 31];
            }
        }

        // ---- mma over the chunk in smem ----
#pragma unroll
        for (int ks = 0; ks < KCH; ks += 16) {
            uint32_t ah[4], al[4];
            uint32_t aoff = (uint32_t)((arow * XSTR + ks + acol) * 2);
            ldsm_x4(ah, xhi_b + aoff);
            ldsm_x4(al, xlo_b + aoff);
#pragma unroll
            for (int np = 0; np < 4; np++) {
                uint32_t bh[4], bl[4];
                uint32_t boff = (uint32_t)(((ks + bk) * WSTR + wc * 64 + np * 16 + bn) * 2);
                ldsm_x4_t(bh, whi_b + boff);
                ldsm_x4_t(bl, wlo_b + boff);
                mma_bf16(c[2 * np],     ah, bh[0], bh[1]);
                mma_bf16(c[2 * np],     ah, bl[0], bl[1]);
                mma_bf16(c[2 * np],     al, bh[0], bh[1]);
                mma_bf16(c[2 * np + 1], ah, bh[2], bh[3]);
                mma_bf16(c[2 * np + 1], ah, bl[2], bl[3]);
                mma_bf16(c[2 * np + 1], al, bh[2], bh[3]);
            }
        }
        __syncthreads();
    }

    // ---- epilogue: h (fp16) store + edge partials over this warp's 64 cols ----
    const int gid = lane >> 2;
    const int tig = lane & 3;
    const int r0 = m0 + wr * 16 + gid;     // global rows
    const int r1 = r0 + 8;
    const int lrow0 = wr * 16 + gid;       // local rows within tile
    const int lrow1 = lrow0 + 8;

    float ss0 = 0.f, sd0 = 0.f, ss1 = 0.f, sd1 = 0.f;
#pragma unroll
    for (int nt = 0; nt < 8; nt++) {
        int col = wc * 64 + nt * 8 + tig * 2;
        __half2 p0 = __floats2half2_rn(c[nt][0], c[nt][1]);
        __half2 p1 = __floats2half2_rn(c[nt][2], c[nt][3]);
        *reinterpret_cast<__half2*>(g_hh + (size_t)r0 * F + col) = p0;
        *reinterpret_cast<__half2*>(g_hh + (size_t)r1 * F + col) = p1;
        float as0 = a_src[col], as1 = a_src[col + 1];
        float ad0 = a_dst[col], ad1 = a_dst[col + 1];
        ss0 += c[nt][0] * as0 + c[nt][1] * as1;
        sd0 += c[nt][0] * ad0 + c[nt][1] * ad1;
        ss1 += c[nt][2] * as0 + c[nt][3] * as1;
        sd1 += c[nt][2] * ad0 + c[nt][3] * ad1;
    }
#pragma unroll
    for (int o = 1; o <= 2; o <<= 1) {
        ss0 += __shfl_xor_sync(0xFFFFFFFFu, ss0, o);
        sd0 += __shfl_xor_sync(0xFFFFFFFFu, sd0, o);
        ss1 += __shfl_xor_sync(0xFFFFFFFFu, ss1, o);
        sd1 += __shfl_xor_sync(0xFFFFFFFFu, sd1, o);
    }
    if (tig == 0) {
        s_es[wc][lrow0] = ss0;
        s_ed[wc][lrow0] = sd0;
        s_es[wc][lrow1] = ss1;
        s_ed[wc][lrow1] = sd1;
    }
    __syncthreads();
    if (tid < TM) {
        g_esrc[m0 + tid] = s_es[0][tid] + s_es[1][tid];
        g_edst[m0 + tid] = s_ed[0][tid] + s_ed[1][tid];
    }
}

// ---------------------------------------------------------------------------
// Kernel 2: block = graph row i; its 8 warps = the 8 batches (b = warp id).
// R13 structure (proven 24.0us) + vectorized int4/float4 shared reads in
// the gather loop (4x LDS.128 replace 16x scalar LDS per 8-nbr batch).
// ---------------------------------------------------------------------------
__global__ __launch_bounds__(256) void agg_kernel(float* __restrict__ out) {
    __shared__ __align__(16) int   s_idx[MAXN];
    __shared__ __align__(16) float s_w[B][MAXN];

    const int i = blockIdx.x;              // graph row
    const int w = threadIdx.x >> 5;        // warp id == batch b
    const int lane = threadIdx.x & 31;
    const int nnz = g_nnz[i];

    // Cooperative index load (once per block, shared by all 8 warps)
    for (int j = threadIdx.x; j < nnz; j += 256)
        s_idx[j] = g_nbr[i * MAXN + j];
    __syncthreads();

    const int wg = w * N + i;              // flat (b, i) row id
    const float ei = g_esrc[wg];
    const float* __restrict__ edst_b = g_edst + w * N;

    // Pass 1: logits -> shared, warp max
    float m = -1e30f;
    for (int j = lane; j < nnz; j += 32) {
        float v = ei + edst_b[s_idx[j]];
        v = (v >= 0.f) ? v : ALPHA * v;    // LeakyReLU
        s_w[w][j] = v;
        m = fmaxf(m, v);
    }
#pragma unroll
    for (int o = 16; o; o >>= 1) m = fmaxf(m, __shfl_xor_sync(0xFFFFFFFFu, m, o));

    __syncwarp();
    // Pass 2: exp + warp sum
    float sum = 0.f;
    for (int j = lane; j < nnz; j += 32) {
        float e = expf(s_w[w][j] - m);
        s_w[w][j] = e;
        sum += e;
    }
#pragma unroll
    for (int o = 16; o; o >>= 1) sum += __shfl_xor_sync(0xFFFFFFFFu, sum, o);
    const float inv = 1.f / sum;
    __syncwarp();

    // Pass 3: gather-aggregate (fp16 rows, fp32 accumulate), unroll 8,
    // vectorized LDS.128 for indices and weights.
    const __half* __restrict__ hb = g_hh + (size_t)w * N * F;
    float4 acc = {0.f, 0.f, 0.f, 0.f};
    int j = 0;
    for (; j + 8 <= nnz; j += 8) {
        int4 ia = *reinterpret_cast<const int4*>(&s_idx[j]);
        int4 ib = *reinterpret_cast<const int4*>(&s_idx[j + 4]);
        float4 wa = *reinterpret_cast<const float4*>(&s_w[w][j]);
        float4 wb = *reinterpret_cast<const float4*>(&s_w[w][j + 4]);
        uint2 r[8];
        r[0] = reinterpret_cast<const uint2*>(hb + (size_t)ia.x * F)[lane];
        r[1] = reinterpret_cast<const uint2*>(hb + (size_t)ia.y * F)[lane];
        r[2] = reinterpret_cast<const uint2*>(hb + (size_t)ia.z * F)[lane];
        r[3] = reinterpret_cast<const uint2*>(hb + (size_t)ia.w * F)[lane];
        r[4] = reinterpret_cast<const uint2*>(hb + (size_t)ib.x * F)[lane];
        r[5] = reinterpret_cast<const uint2*>(hb + (size_t)ib.y * F)[lane];
        r[6] = reinterpret_cast<const uint2*>(hb + (size_t)ib.z * F)[lane];
        r[7] = reinterpret_cast<const uint2*>(hb + (size_t)ib.w * F)[lane];
        float wt[8] = {wa.x, wa.y, wa.z, wa.w, wb.x, wb.y, wb.z, wb.w};
#pragma unroll
        for (int q = 0; q < 8; q++) {
            float2 a = __half22float2(*reinterpret_cast<__half2*>(&r[q].x));
            float2 bb = __half22float2(*reinterpret_cast<__half2*>(&r[q].y));
            acc.x += wt[q] * a.x;  acc.y += wt[q] * a.y;
            acc.z += wt[q] * bb.x; acc.w += wt[q] * bb.y;
        }
    }
    for (; j < nnz; j++) {
        int ij = s_idx[j];
        float wj = s_w[w][j];
        uint2 r = reinterpret_cast<const uint2*>(hb + (size_t)ij * F)[lane];
        float2 a = __half22float2(*reinterpret_cast<__half2*>(&r.x));
        float2 bb = __half22float2(*reinterpret_cast<__half2*>(&r.y));
        acc.x += wj * a.x; acc.y += wj * a.y; acc.z += wj * bb.x; acc.w += wj * bb.y;
    }

    acc.x *= inv; acc.y *= inv; acc.z *= inv; acc.w *= inv;
    // ELU (alpha = 1)
    float4 r;
    r.x = (acc.x > 0.f) ? acc.x : expm1f(acc.x);
    r.y = (acc.y > 0.f) ? acc.y : expm1f(acc.y);
    r.z = (acc.z > 0.f) ? acc.z : expm1f(acc.z);
    r.w = (acc.w > 0.f) ? acc.w : expm1f(acc.w);
    reinterpret_cast<float4*>(out + (size_t)wg * F)[lane] = r;
}

// ---------------------------------------------------------------------------
extern "C" void kernel_launch(void* const* d_in, const int* in_sizes, int n_in,
                              void* d_out, int out_size) {
    const float* x     = (const float*)d_in[0];  // [B, N, F]
    const float* adj   = (const float*)d_in[1];  // [N, N]
    const float* W     = (const float*)d_in[2];  // [F, F]
    const float* a_src = (const float*)d_in[3];  // [F]
    const float* a_dst = (const float*)d_in[4];  // [F]
    float* out = (float*)d_out;                  // [B, N, F]

    (void)in_sizes; (void)n_in; (void)out_size;

    fused_gemm_adj_kernel<<<ADJ_BLOCKS + GEMM_BLOCKS, 256>>>(x, adj, W, a_src, a_dst);
    agg_kernel<<<N, 256>>>(out);
}

// round 17
// speedup vs baseline: 1.0968x; 1.0968x over previous
#include <cuda_runtime.h>
#include <cuda_fp16.h>
#include <cuda_bf16.h>
#include <cstdint>

// Problem constants (fixed shapes)
#define B 8
#define N 2048
#define F 128            // F_IN == F_OUT == 128
#define MAXN 192         // max neighbors per row (mean ~42)
#define ALPHA 0.2f

// Scratch (no cudaMalloc allowed)
__device__ __align__(16) __half g_hh[B * N * F];   // 4 MB, fp16 copy of h
__device__ float g_esrc[B * N];
__device__ float g_edst[B * N];
__device__ __align__(16) int g_nbr[N * MAXN];
__device__ int   g_nnz[N];

// ---------------------------------------------------------------------------
// mma / ldmatrix helpers
// ---------------------------------------------------------------------------
__device__ __forceinline__ void ldsm_x4(uint32_t* r, uint32_t addr) {
    asm volatile("ldmatrix.sync.aligned.m8n8.x4.shared.b16 {%0,%1,%2,%3}, [%4];"
                 : "=r"(r[0]), "=r"(r[1]), "=r"(r[2]), "=r"(r[3]) : "r"(addr));
}
__device__ __forceinline__ void ldsm_x4_t(uint32_t* r, uint32_t addr) {
    asm volatile("ldmatrix.sync.aligned.m8n8.x4.trans.shared.b16 {%0,%1,%2,%3}, [%4];"
                 : "=r"(r[0]), "=r"(r[1]), "=r"(r[2]), "=r"(r[3]) : "r"(addr));
}
__device__ __forceinline__ void mma_bf16(float* c, const uint32_t* a,
                                         uint32_t b0, uint32_t b1) {
    asm volatile(
        "mma.sync.aligned.m16n8k16.row.col.f32.bf16.bf16.f32 "
        "{%0,%1,%2,%3}, {%4,%5,%6,%7}, {%8,%9}, {%0,%1,%2,%3};"
        : "+f"(c[0]), "+f"(c[1]), "+f"(c[2]), "+f"(c[3])
        : "r"(a[0]), "r"(a[1]), "r"(a[2]), "r"(a[3]), "r"(b0), "r"(b1));
}
__device__ __forceinline__ uint32_t pack_bf16(__nv_bfloat16 a, __nv_bfloat16 b) {
    __nv_bfloat162 t;
    t.x = a; t.y = b;
    return *reinterpret_cast<uint32_t*>(&t);
}

// ---------------------------------------------------------------------------
// Fat kernel (256 thr = 8 warps):
//   blocks [0,256)   -> bf16-split mma GEMM, 64 rows each (warp = 16r x 64c)
//                       with smem-staged COALESCED fp16 h epilogue
//   blocks [256,512) -> adj bitmask compaction, 8 rows each (1/warp)
// ---------------------------------------------------------------------------
#define GEMM_BLOCKS 256
#define ADJ_BLOCKS 256
#define TM 64
#define KCH 32
#define XSTR 40      // bf16 elems per X smem row
#define WSTR 136     // bf16 elems per W smem row
#define HSTR 136     // half elems per staged-h row: 272 B, 16B-aligned rows

__global__ __launch_bounds__(256) void fused_gemm_adj_kernel(
    const float* __restrict__ x,
    const float* __restrict__ adj,
    const float* __restrict__ W,
    const float* __restrict__ a_src,
    const float* __restrict__ a_dst) {

    if (blockIdx.x >= GEMM_BLOCKS) {
        // ------- adjacency: single-pass bitmask compaction, warp per row -----
        int i = (blockIdx.x - GEMM_BLOCKS) * 8 + (threadIdx.x >> 5);
        int lane = threadIdx.x & 31;
        const float4* row4 = reinterpret_cast<const float4*>(adj + (size_t)i * N);
        unsigned msk0 = 0u, msk1 = 0u;
        int cnt = 0;
#pragma unroll
        for (int q = 0; q < 16; q++) {
            float4 v = row4[lane * 16 + q];
            int base = q * 4;
            float vv[4] = {v.x, v.y, v.z, v.w};
#pragma unroll
            for (int k = 0; k < 4; k++) {
                int bit = base + k;
                bool p = (vv[k] != 0.f) || (lane * 64 + bit == i);
                if (p) {
                    if (bit < 32) msk0 |= (1u << bit);
                    else          msk1 |= (1u << (bit - 32));
                    cnt++;
                }
            }
        }
        int off = cnt;
#pragma unroll
        for (int d = 1; d < 32; d <<= 1) {
            int t = __shfl_up_sync(0xFFFFFFFFu, off, d);
            if (lane >= d) off += t;
        }
        int total = __shfl_sync(0xFFFFFFFFu, off, 31);
        off -= cnt;
        int pos = off;
        unsigned mm = msk0;
        while (mm) {
            int bit = __ffs(mm) - 1;
            mm &= mm - 1;
            if (pos < MAXN) g_nbr[i * MAXN + pos] = lane * 64 + bit;
            pos++;
        }
        mm = msk1;
        while (mm) {
            int bit = __ffs(mm) - 1;
            mm &= mm - 1;
            if (pos < MAXN) g_nbr[i * MAXN + pos] = lane * 64 + 32 + bit;
            pos++;
        }
        if (lane == 31) g_nnz[i] = total < MAXN ? total : MAXN;
        return;
    }

    // ---------------- GEMM path: 8 warps, warp = 16 rows x 64 cols ----------
    __shared__ __align__(16) __nv_bfloat16 Xhi[TM * XSTR];
    __shared__ __align__(16) __nv_bfloat16 Xlo[TM * XSTR];
    __shared__ __align__(16) __nv_bfloat16 Whi[KCH * WSTR];
    __shared__ __align__(16) __nv_bfloat16 Wlo[KCH * WSTR];
    __shared__ __align__(16) __half s_h[TM * HSTR];   // staged h tile (padded)
    __shared__ float s_es[2][TM];   // edge partials per N-half
    __shared__ float s_ed[2][TM];

    const int tid = threadIdx.x;
    const int w = tid >> 5;
    const int lane = tid & 31;
    const int wr = w >> 1;         // row group 0..3 (16 rows each)
    const int wc = w & 1;          // col half 0..1 (64 cols each)
    const int m0 = blockIdx.x * TM;

    const int lm = lane >> 3;
    const int lr = lane & 7;
    const int arow = wr * 16 + ((lm & 1) << 3) + lr;
    const int acol = (lm >> 1) << 3;
    const int bk = ((lm & 1) << 3) + lr;
    const int bn = (lm >> 1) << 3;

    const uint32_t xhi_b = (uint32_t)__cvta_generic_to_shared(Xhi);
    const uint32_t xlo_b = (uint32_t)__cvta_generic_to_shared(Xlo);
    const uint32_t whi_b = (uint32_t)__cvta_generic_to_shared(Whi);
    const uint32_t wlo_b = (uint32_t)__cvta_generic_to_shared(Wlo);

    float c[8][4];
#pragma unroll
    for (int nt = 0; nt < 8; nt++)
#pragma unroll
        for (int q = 0; q < 4; q++) c[nt][q] = 0.f;

#pragma unroll
    for (int k0 = 0; k0 < F; k0 += KCH) {
        // ---- X chunk [64 rows x 32 k]: load fp32, split inline (2/thread) ----
#pragma unroll
        for (int it = 0; it < 2; it++) {
            int l = tid + it * 256;
            int row = l >> 3;
            int c4 = l & 7;
            float4 v = reinterpret_cast<const float4*>(
                x + (size_t)(m0 + row) * F + k0)[c4];
            float vv[4] = {v.x, v.y, v.z, v.w};
            __nv_bfloat16 hi[4], lo[4];
#pragma unroll
            for (int j = 0; j < 4; j++) {
                hi[j] = __float2bfloat16_rn(vv[j]);
                lo[j] = __float2bfloat16_rn(vv[j] - __bfloat162float(hi[j]));
            }
            int eoff = row * XSTR + c4 * 4;
            uint2 ph = {pack_bf16(hi[0], hi[1]), pack_bf16(hi[2], hi[3])};
            uint2 pl = {pack_bf16(lo[0], lo[1]), pack_bf16(lo[2], lo[3])};
            *reinterpret_cast<uint2*>(Xhi + eoff) = ph;
            *reinterpret_cast<uint2*>(Xlo + eoff) = pl;
        }
        // ---- W chunk [32 k x 128 n]: load fp32, split inline (4/thread) ----
#pragma unroll
        for (int it = 0; it < 4; it++) {
            int l = tid + it * 256;
            int kk = l >> 5;
            int c4 = l & 31;
            float4 v = reinterpret_cast<const float4*>(
                W + (size_t)(k0 + kk) * F)[c4];
            float vv[4] = {v.x, v.y, v.z, v.w};
            __nv_bfloat16 hi[4], lo[4];
#pragma unroll
            for (int j = 0; j < 4; j++) {
                hi[j] = __float2bfloat16_rn(vv[j]);
                lo[j] = __float2bfloat16_rn(vv[j] - __bfloat162float(hi[j]));
            }
            int eoff = kk * WSTR + c4 * 4;
            uint2 ph = {pack_bf16(hi[0], hi[1]), pack_bf16(hi[2], hi[3])};
            uint2 pl = {pack_bf16(lo[0], lo[1]), pack_bf16(lo[2], lo[3])};
            *reinterpret_cast<uint2*>(Whi + eoff) = ph;
            *reinterpret_cast<uint2*>(Wlo + eoff) = pl;
        }
        __syncthreads();

#pragma unroll
        for (int ks = 0; ks < KCH; ks += 16) {
            uint32_t ah[4], al[4];
            uint32_t aoff = (uint32_t)((arow * XSTR + ks + acol) * 2);
            ldsm_x4(ah, xhi_b + aoff);
            ldsm_x4(al, xlo_b + aoff);
#pragma unroll
            for (int np = 0; np < 4; np++) {
                uint32_t bh[4], bl[4];
                uint32_t boff = (uint32_t)(((ks + bk) * WSTR + wc * 64 + np * 16 + bn) * 2);
                ldsm_x4_t(bh, whi_b + boff);
                ldsm_x4_t(bl, wlo_b + boff);
                mma_bf16(c[2 * np],     ah, bh[0], bh[1]);
                mma_bf16(c[2 * np],     ah, bl[0], bl[1]);
                mma_bf16(c[2 * np],     al, bh[0], bh[1]);
                mma_bf16(c[2 * np + 1], ah, bh[2], bh[3]);
                mma_bf16(c[2 * np + 1], ah, bl[2], bl[3]);
                mma_bf16(c[2 * np + 1], al, bh[2], bh[3]);
            }
        }
        __syncthreads();
    }

    // ---- epilogue part 1: stage h tile in smem + edge partials ----
    const int gid = lane >> 2;
    const int tig = lane & 3;
    const int lrow0 = wr * 16 + gid;       // local rows within tile
    const int lrow1 = lrow0 + 8;

    float ss0 = 0.f, sd0 = 0.f, ss1 = 0.f, sd1 = 0.f;
#pragma unroll
    for (int nt = 0; nt < 8; nt++) {
        int col = wc * 64 + nt * 8 + tig * 2;
        __half2 p0 = __floats2half2_rn(c[nt][0], c[nt][1]);
        __half2 p1 = __floats2half2_rn(c[nt][2], c[nt][3]);
        *reinterpret_cast<__half2*>(s_h + lrow0 * HSTR + col) = p0;
        *reinterpret_cast<__half2*>(s_h + lrow1 * HSTR + col) = p1;
        float as0 = a_src[col], as1 = a_src[col + 1];
        float ad0 = a_dst[col], ad1 = a_dst[col + 1];
        ss0 += c[nt][0] * as0 + c[nt][1] * as1;
        sd0 += c[nt][0] * ad0 + c[nt][1] * ad1;
        ss1 += c[nt][2] * as0 + c[nt][3] * as1;
        sd1 += c[nt][2] * ad0 + c[nt][3] * ad1;
    }
#pragma unroll
    for (int o = 1; o <= 2; o <<= 1) {
        ss0 += __shfl_xor_sync(0xFFFFFFFFu, ss0, o);
        sd0 += __shfl_xor_sync(0xFFFFFFFFu, sd0, o);
        ss1 += __shfl_xor_sync(0xFFFFFFFFu, ss1, o);
        sd1 += __shfl_xor_sync(0xFFFFFFFFu, sd1, o);
    }
    if (tig == 0) {
        s_es[wc][lrow0] = ss0;
        s_ed[wc][lrow0] = sd0;
        s_es[wc][lrow1] = ss1;
        s_ed[wc][lrow1] = sd1;
    }
    __syncthreads();

    // ---- epilogue part 2: coalesced h store (LDS.128 -> STG.128) ----
    // 64 rows x 128 halves = 1024 uint4; 4 per thread. Row stride 272 B
    // keeps every uint4 16B-aligned (seg*16 + row*272).
#pragma unroll
    for (int it = 0; it < 4; it++) {
        int idx = tid + it * 256;
        int row = idx >> 4;          // 0..63
        int seg = idx & 15;          // uint4 index within row (8 halves each)
        uint4 v = *reinterpret_cast<const uint4*>(s_h + row * HSTR + seg * 8);
        reinterpret_cast<uint4*>(g_hh + (size_t)(m0 + row) * F)[seg] = v;
    }
    if (tid < TM) {
        g_esrc[m0 + tid] = s_es[0][tid] + s_es[1][tid];
        g_edst[m0 + tid] = s_ed[0][tid] + s_ed[1][tid];
    }
}

// ---------------------------------------------------------------------------
// Kernel 2: block = graph row i; its 8 warps = the 8 batches (b = warp id).
// R15 agg (best measured variant, 23.87us): shared index list + vectorized
// LDS.128 index/weight reads + unroll-8 uint2 gathers, fp32 accumulate.
// ---------------------------------------------------------------------------
__global__ __launch_bounds__(256) void agg_kernel(float* __restrict__ out) {
    __shared__ __align__(16) int   s_idx[MAXN];
    __shared__ __align__(16) float s_w[B][MAXN];

    const int i = blockIdx.x;              // graph row
    const int w = threadIdx.x >> 5;        // warp id == batch b
    const int lane = threadIdx.x & 31;
    const int nnz = g_nnz[i];

    // Cooperative index load (once per block, shared by all 8 warps)
    for (int j = threadIdx.x; j < nnz; j += 256)
        s_idx[j] = g_nbr[i * MAXN + j];
    __syncthreads();

    const int wg = w * N + i;              // flat (b, i) row id
    const float ei = g_esrc[wg];
    const float* __restrict__ edst_b = g_edst + w * N;

    // Pass 1: logits -> shared, warp max
    float m = -1e30f;
    for (int j = lane; j < nnz; j += 32) {
        float v = ei + edst_b[s_idx[j]];
        v = (v >= 0.f) ? v : ALPHA * v;    // LeakyReLU
        s_w[w][j] = v;
        m = fmaxf(m, v);
    }
#pragma unroll
    for (int o = 16; o; o >>= 1) m = fmaxf(m, __shfl_xor_sync(0xFFFFFFFFu, m, o));

    __syncwarp();
    // Pass 2: exp + warp sum
    float sum = 0.f;
    for (int j = lane; j < nnz; j += 32) {
        float e = expf(s_w[w][j] - m);
        s_w[w][j] = e;
        sum += e;
    }
#pragma unroll
    for (int o = 16; o; o >>= 1) sum += __shfl_xor_sync(0xFFFFFFFFu, sum, o);
    const float inv = 1.f / sum;
    __syncwarp();

    // Pass 3: gather-aggregate (fp16 rows, fp32 accumulate), unroll 8.
    const __half* __restrict__ hb = g_hh + (size_t)w * N * F;
    float4 acc = {0.f, 0.f, 0.f, 0.f};
    int j = 0;
    for (; j + 8 <= nnz; j += 8) {
        int4 ia = *reinterpret_cast<const int4*>(&s_idx[j]);
        int4 ib = *reinterpret_cast<const int4*>(&s_idx[j + 4]);
        float4 wa = *reinterpret_cast<const float4*>(&s_w[w][j]);
        float4 wb = *reinterpret_cast<const float4*>(&s_w[w][j + 4]);
        uint2 r[8];
        r[0] = reinterpret_cast<const uint2*>(hb + (size_t)ia.x * F)[lane];
        r[1] = reinterpret_cast<const uint2*>(hb + (size_t)ia.y * F)[lane];
        r[2] = reinterpret_cast<const uint2*>(hb + (size_t)ia.z * F)[lane];
        r[3] = reinterpret_cast<const uint2*>(hb + (size_t)ia.w * F)[lane];
        r[4] = reinterpret_cast<const uint2*>(hb + (size_t)ib.x * F)[lane];
        r[5] = reinterpret_cast<const uint2*>(hb + (size_t)ib.y * F)[lane];
        r[6] = reinterpret_cast<const uint2*>(hb + (size_t)ib.z * F)[lane];
        r[7] = reinterpret_cast<const uint2*>(hb + (size_t)ib.w * F)[lane];
        float wt[8] = {wa.x, wa.y, wa.z, wa.w, wb.x, wb.y, wb.z, wb.w};
#pragma unroll
        for (int q = 0; q < 8; q++) {
            float2 a = __half22float2(*reinterpret_cast<__half2*>(&r[q].x));
            float2 bb = __half22float2(*reinterpret_cast<__half2*>(&r[q].y));
            acc.x += wt[q] * a.x;  acc.y += wt[q] * a.y;
            acc.z += wt[q] * bb.x; acc.w += wt[q] * bb.y;
        }
    }
    for (; j < nnz; j++) {
        int ij = s_idx[j];
        float wj = s_w[w][j];
        uint2 r = reinterpret_cast<const uint2*>(hb + (size_t)ij * F)[lane];
        float2 a = __half22float2(*reinterpret_cast<__half2*>(&r.x));
        float2 bb = __half22float2(*reinterpret_cast<__half2*>(&r.y));
        acc.x += wj * a.x; acc.y += wj * a.y; acc.z += wj * bb.x; acc.w += wj * bb.y;
    }

    acc.x *= inv; acc.y *= inv; acc.z *= inv; acc.w *= inv;
    // ELU (alpha = 1)
    float4 r;
    r.x = (acc.x > 0.f) ? acc.x : expm1f(acc.x);
    r.y = (acc.y > 0.f) ? acc.y : expm1f(acc.y);
    r.z = (acc.z > 0.f) ? acc.z : expm1f(acc.z);
    r.w = (acc.w > 0.f) ? acc.w : expm1f(acc.w);
    reinterpret_cast<float4*>(out + (size_t)wg * F)[lane] = r;
}

// ---------------------------------------------------------------------------
extern "C" void kernel_launch(void* const* d_in, const int* in_sizes, int n_in,
                              void* d_out, int out_size) {
    const float* x     = (const float*)d_in[0];  // [B, N, F]
    const float* adj   = (const float*)d_in[1];  // [N, N]
    const float* W     = (const float*)d_in[2];  // [F, F]
    const float* a_src = (const float*)d_in[3];  // [F]
    const float* a_dst = (const float*)d_in[4];  // [F]
    float* out = (float*)d_out;                  // [B, N, F]

    (void)in_sizes; (void)n_in; (void)out_size;

    fused_gemm_adj_kernel<<<GEMM_BLOCKS + ADJ_BLOCKS, 256>>>(x, adj, W, a_src, a_dst);
    agg_kernel<<<N, 256>>>(out);
}